// round 11
// baseline (speedup 1.0000x reference)
#include <cuda_runtime.h>
#include <cstdint>

#define NPTS     16384
#define NB       256
#define XMIN     (-4.0f)
#define BW       0.03125f           // 8/256, exact in binary
#define INVBW    32.0f
#define HBLOCKS  64                 // hist/scatter blocks (32 per set)
#define HTHREADS 256
#define PPB      512                // points per hist/scatter block
#define GSIZE    256                // queries per group
#define NGRP     128                // 64 per direction
#define MTHREADS 64                 // phase-A block size
#define KA       4                  // queries per thread
#define NTILE    8                  // window tiles per group
#define TILE     256                // ranks per tile  (window = 2048 ranks)
#define WHALF    1024
#define RBLOCKS  128
#define RTHREADS 256

#define POS_INF __int_as_float(0x7f800000)

// ---------------- persistent scratch (rewritten every call) ----------------
__device__ int    g_part[HBLOCKS][NB];       // per-block partial histograms
__device__ int    g_boff[2][NB + 1];         // bucket start offsets
__device__ int    g_cur[2][NB];              // scatter cursors
__device__ float4 g_sorted[2][NPTS];         // (x,y,z,|p|^2), bucket-sorted by x
__device__ float  g_tmin[2 * NPTS][NTILE];   // per-(query,tile) partial mins (1 MB)
__device__ float  g_partial[RBLOCKS];        // resolve-block sums

__device__ __forceinline__ int bucket_of(float x) {
    int b = (int)floorf((x - XMIN) * INVBW);
    return min(max(b, 0), NB - 1);
}
// unseen-left points (rank < lo) lie in buckets <= bucket_of(B[lo].x): x < right edge
__device__ __forceinline__ float right_edge(int b) {
    return (b >= NB - 1) ? 1e30f : (XMIN + (float)(b + 1) * BW);
}
// unseen-right points (rank >= hi) lie in buckets >= bucket_of(B[hi-1].x): x >= left edge
__device__ __forceinline__ float left_edge(int b) {
    return (b <= 0) ? -1e30f : (XMIN + (float)b * BW);
}

// ---------------- packed f32x2 helpers ----------------
__device__ __forceinline__ unsigned long long pack2(float lo, float hi) {
    unsigned long long r;
    asm("mov.b64 %0, {%1, %2};" : "=l"(r) : "f"(lo), "f"(hi));
    return r;
}
__device__ __forceinline__ unsigned long long fma2(unsigned long long a,
                                                   unsigned long long b,
                                                   unsigned long long c) {
    unsigned long long d;
    asm("fma.rn.f32x2 %0, %1, %2, %3;" : "=l"(d) : "l"(a), "l"(b), "l"(c));
    return d;
}
__device__ __forceinline__ void unpack2(unsigned long long v, float& lo, float& hi) {
    asm("mov.b64 {%0, %1}, %2;" : "=f"(lo), "=f"(hi) : "l"(v));
}

__device__ __forceinline__ int window_base(int grp_local) {
    int c = grp_local * GSIZE + GSIZE / 2;
    int b = c - WHALF;
    return min(max(b, 0), NPTS - NTILE * TILE);
}

// ---------------- kernel 1: partial histograms ----------------
__global__ void __launch_bounds__(HTHREADS)
hist_kernel(const float* __restrict__ pred, const float* __restrict__ targ) {
    __shared__ int h[NB];
    const int set   = blockIdx.x >> 5;
    const int slice = blockIdx.x & 31;
    const float* __restrict__ src = set ? targ : pred;
    const int tid = threadIdx.x;
    h[tid] = 0;
    __syncthreads();
#pragma unroll
    for (int r = 0; r < PPB / HTHREADS; r++) {
        const int i = slice * PPB + r * HTHREADS + tid;
        atomicAdd(&h[bucket_of(src[3 * i])], 1);
    }
    __syncthreads();
    g_part[blockIdx.x][tid] = h[tid];
}

// ---------------- kernel 2: prefix scan ----------------
__global__ void __launch_bounds__(2 * NB)
scan_kernel() {
    __shared__ int sVal[2 * NB];
    const int tid = threadIdx.x;
    const int set = tid >> 8;
    const int b   = tid & (NB - 1);

    int cnt = 0;
#pragma unroll 8
    for (int k = 0; k < 32; k++) cnt += g_part[set * 32 + k][b];
    sVal[tid] = cnt;
    __syncthreads();
    for (int st = 1; st < NB; st <<= 1) {
        int add = (b >= st) ? sVal[tid - st] : 0;
        __syncthreads();
        sVal[tid] += add;
        __syncthreads();
    }
    const int excl = sVal[tid] - cnt;
    g_boff[set][b] = excl;
    g_cur[set][b]  = excl;
    if (b == NB - 1) g_boff[set][NB] = sVal[tid];
}

// ---------------- kernel 3: scatter into bucket-sorted order --------------
__global__ void __launch_bounds__(HTHREADS)
scatter_kernel(const float* __restrict__ pred, const float* __restrict__ targ) {
    const int set   = blockIdx.x >> 5;
    const int slice = blockIdx.x & 31;
    const float* __restrict__ src = set ? targ : pred;
    const int tid = threadIdx.x;
#pragma unroll
    for (int r = 0; r < PPB / HTHREADS; r++) {
        const int i = slice * PPB + r * HTHREADS + tid;
        float x = src[3 * i + 0];
        float y = src[3 * i + 1];
        float z = src[3 * i + 2];
        int pos = atomicAdd(&g_cur[set][bucket_of(x)], 1);
        g_sorted[set][pos] = make_float4(x, y, z, x * x + y * y + z * z);
    }
}

// ---------------- kernel 4: phase A — flat windowed tile scan -------------
// 1024 CTAs of 64 threads: block = (group of 256 queries, tile of 256 ranks).
// KA=4 queries per thread: every 4-LDS.128 batch feeds 24 packed FFMA2, the
// mix that measured 60% fma on the brute kernel (vs 27% with KA=1).
__global__ void __launch_bounds__(MTHREADS)
phasea_kernel() {
    __shared__ __align__(16) float sx[TILE], sy[TILE], sz[TILE], sc[TILE];

    const int grp  = blockIdx.x >> 3;          // 0..127
    const int tile = blockIdx.x & 7;
    const int dir  = grp >> 6;
    const int grpl = grp & 63;
    const int aset = dir, bset = 1 - dir;
    const int tid  = threadIdx.x;

    const int t0 = window_base(grpl) + tile * TILE;
    const float4* __restrict__ B = g_sorted[bset];

    // stage tile (SoA): 64 threads x 4 float4, coalesced
#pragma unroll
    for (int r = 0; r < TILE / MTHREADS; r++) {
        const int s = tid + r * MTHREADS;
        float4 v = B[t0 + s];
        sx[s] = v.x; sy[s] = v.y; sz[s] = v.z; sc[s] = v.w;
    }

    // load KA query points
    const int q0 = grpl * GSIZE + tid;
    unsigned long long ax2[KA], ay2[KA], az2[KA];
    float mlo[KA], mhi[KA];
#pragma unroll
    for (int k = 0; k < KA; k++) {
        const float4 a = g_sorted[aset][q0 + k * MTHREADS];
        ax2[k] = pack2(-2.0f * a.x, -2.0f * a.x);
        ay2[k] = pack2(-2.0f * a.y, -2.0f * a.y);
        az2[k] = pack2(-2.0f * a.z, -2.0f * a.z);
        mlo[k] = POS_INF;
        mhi[k] = POS_INF;
    }
    __syncthreads();

#pragma unroll 4
    for (int j = 0; j < TILE; j += 4) {
        ulonglong2 vx = *(const ulonglong2*)&sx[j];
        ulonglong2 vy = *(const ulonglong2*)&sy[j];
        ulonglong2 vz = *(const ulonglong2*)&sz[j];
        ulonglong2 vc = *(const ulonglong2*)&sc[j];
#pragma unroll
        for (int k = 0; k < KA; k++) {
            unsigned long long s01 = fma2(ax2[k], vx.x, fma2(ay2[k], vy.x, fma2(az2[k], vz.x, vc.x)));
            unsigned long long s23 = fma2(ax2[k], vx.y, fma2(ay2[k], vy.y, fma2(az2[k], vz.y, vc.y)));
            float s0, s1, s2, s3;
            unpack2(s01, s0, s1);
            unpack2(s23, s2, s3);
            mlo[k] = fminf(mlo[k], fminf(s0, s2));
            mhi[k] = fminf(mhi[k], fminf(s1, s3));
        }
    }

#pragma unroll
    for (int k = 0; k < KA; k++)
        g_tmin[dir * NPTS + q0 + k * MTHREADS][tile] = fminf(mlo[k], mhi[k]);
}

// ---------------- kernel 5: resolve + fused exact fallback ----------------
// One thread per query: reduce 8 tile partials, conservative bucket-edge bound
// check. Unresolved queries go to a per-block smem list; the whole block then
// does an exact cooperative full scan for each listed query (expected: a
// handful chip-wide). Block partial sums -> g_partial.
__global__ void __launch_bounds__(RTHREADS)
resolve_kernel() {
    __shared__ float sRed[RTHREADS / 32];
    __shared__ int   sList[RTHREADS];
    __shared__ int   sCnt;
    __shared__ float sFb;

    const int tid  = threadIdx.x;
    if (tid == 0) { sCnt = 0; sFb = 0.0f; }
    __syncthreads();

    const int gq   = blockIdx.x * RTHREADS + tid;  // 0..32767
    const int dir  = gq >> 14;
    const int q    = gq & (NPTS - 1);
    const int aset = dir, bset = 1 - dir;

    float m = POS_INF;
#pragma unroll
    for (int t = 0; t < NTILE; t++) m = fminf(m, g_tmin[gq][t]);

    const float4 a = g_sorted[aset][q];
    const float bound = fmaxf(a.w + m, 0.0f);      // best d^2 in window

    const int wlo = window_base(q >> 8);
    const int whi = wlo + NTILE * TILE;
    const float4* __restrict__ B = g_sorted[bset];

    bool unresolved = false;
    if (wlo > 0) {
        float eL  = right_edge(bucket_of(B[wlo].x));
        float dxl = fmaxf(a.x - eL, 0.0f);
        unresolved |= (dxl * dxl < bound);
    }
    if (whi < NPTS) {
        float eR  = left_edge(bucket_of(B[whi - 1].x));
        float dxr = fmaxf(eR - a.x, 0.0f);
        unresolved |= (dxr * dxr < bound);
    }

    float d = 0.0f;
    if (unresolved) {
        sList[atomicAdd(&sCnt, 1)] = gq;
    } else {
        d = sqrtf(bound);
    }

    // sum resolved distances
#pragma unroll
    for (int s = 16; s > 0; s >>= 1)
        d += __shfl_xor_sync(0xFFFFFFFFu, d, s);
    if ((tid & 31) == 0) sRed[tid >> 5] = d;
    __syncthreads();

    // cooperative exact full scan for each unresolved query in this block
    const int cnt = sCnt;
    for (int i = 0; i < cnt; i++) {
        const int ugq  = sList[i];
        const int udir = ugq >> 14;
        const int uq   = ugq & (NPTS - 1);
        const float4 ua = g_sorted[udir][uq];
        const float amx = -2.0f * ua.x, amy = -2.0f * ua.y, amz = -2.0f * ua.z;
        const float4* __restrict__ UB = g_sorted[1 - udir];

        float mm = POS_INF;
        for (int j = tid; j < NPTS; j += RTHREADS) {
            float4 b = UB[j];
            float s = fmaf(amx, b.x, fmaf(amy, b.y, fmaf(amz, b.z, b.w)));
            mm = fminf(mm, s);
        }
#pragma unroll
        for (int s = 16; s > 0; s >>= 1)
            mm = fminf(mm, __shfl_xor_sync(0xFFFFFFFFu, mm, s));
        __shared__ float sMin[RTHREADS / 32];
        if ((tid & 31) == 0) sMin[tid >> 5] = mm;
        __syncthreads();
        if (tid == 0) {
            float t = POS_INF;
#pragma unroll
            for (int w = 0; w < RTHREADS / 32; w++) t = fminf(t, sMin[w]);
            sFb += sqrtf(fmaxf(ua.w + t, 0.0f));
        }
        __syncthreads();
    }

    if (tid == 0) {
        float t = sFb;
#pragma unroll
        for (int w = 0; w < RTHREADS / 32; w++) t += sRed[w];
        g_partial[blockIdx.x] = t;
    }
}

// ---------------- kernel 6: final sum ----------------
__global__ void __launch_bounds__(RBLOCKS)
final_kernel(float* __restrict__ out) {
    float v = g_partial[threadIdx.x];
#pragma unroll
    for (int s = 16; s > 0; s >>= 1)
        v += __shfl_xor_sync(0xFFFFFFFFu, v, s);
    __shared__ float sRed[RBLOCKS / 32];
    if ((threadIdx.x & 31) == 0) sRed[threadIdx.x >> 5] = v;
    __syncthreads();
    if (threadIdx.x == 0) {
        float t = 0.0f;
#pragma unroll
        for (int w = 0; w < RBLOCKS / 32; w++) t += sRed[w];
        out[0] = t * (1.0f / (float)NPTS);
    }
}

// ---------------- launch ----------------
extern "C" void kernel_launch(void* const* d_in, const int* in_sizes, int n_in,
                              void* d_out, int out_size) {
    const float* pred = (const float*)d_in[0];
    const float* targ = (const float*)d_in[1];
    float* out = (float*)d_out;

    hist_kernel<<<HBLOCKS, HTHREADS>>>(pred, targ);
    scan_kernel<<<1, 2 * NB>>>();
    scatter_kernel<<<HBLOCKS, HTHREADS>>>(pred, targ);
    phasea_kernel<<<NGRP * NTILE, MTHREADS>>>();
    resolve_kernel<<<RBLOCKS, RTHREADS>>>();
    final_kernel<<<1, RBLOCKS>>>(out);
}

// round 12
// speedup vs baseline: 1.5852x; 1.5852x over previous
#include <cuda_runtime.h>
#include <cstdint>

#define NPTS     16384
#define NB       256
#define XMIN     (-4.0f)
#define BW       0.03125f           // 8/256, exact in binary
#define INVBW    32.0f
#define HBLOCKS  64                 // hist/scatter blocks (32 per set)
#define HTHREADS 256
#define PPB      512                // points per hist/scatter block
#define GSIZE    256                // queries per group
#define NGRP     128                // 64 per direction
#define MTHREADS 64                 // phase-A block size
#define KA       4                  // queries per thread
#define NTILE    16                 // window tiles per group
#define TILE     128                // ranks per tile  (window = 2048 ranks)
#define WHALF    1024
#define RBLOCKS  128
#define RTHREADS 256
#define FBBLOCKS 64
#define FBTHREADS 256

#define POS_INF __int_as_float(0x7f800000)

// ---------------- persistent scratch (rewritten every call) ----------------
__device__ int    g_part[HBLOCKS][NB];       // per-block partial histograms
__device__ int    g_boff[2][NB + 1];         // bucket start offsets
__device__ int    g_cur[2][NB];              // scatter cursors
__device__ float4 g_sorted[2][NPTS];         // (x,y,z,|p|^2), bucket-sorted by x
__device__ float  g_tmin[2 * NPTS][NTILE];   // per-(query,tile) partial mins (2 MB)
__device__ float  g_partial[RBLOCKS];        // resolve-block sums
__device__ int    g_unres[2 * NPTS];         // unresolved query list
__device__ int    g_ucnt;                    // list count
__device__ float  g_fsum;                    // fallback sum

__device__ __forceinline__ int bucket_of(float x) {
    int b = (int)floorf((x - XMIN) * INVBW);
    return min(max(b, 0), NB - 1);
}
// unseen-left points (rank < lo) lie in buckets <= bucket_of(B[lo].x): x < right edge
__device__ __forceinline__ float right_edge(int b) {
    return (b >= NB - 1) ? 1e30f : (XMIN + (float)(b + 1) * BW);
}
// unseen-right points (rank >= hi) lie in buckets >= bucket_of(B[hi-1].x): x >= left edge
__device__ __forceinline__ float left_edge(int b) {
    return (b <= 0) ? -1e30f : (XMIN + (float)b * BW);
}

// ---------------- packed f32x2 helpers ----------------
__device__ __forceinline__ unsigned long long pack2(float lo, float hi) {
    unsigned long long r;
    asm("mov.b64 %0, {%1, %2};" : "=l"(r) : "f"(lo), "f"(hi));
    return r;
}
__device__ __forceinline__ unsigned long long fma2(unsigned long long a,
                                                   unsigned long long b,
                                                   unsigned long long c) {
    unsigned long long d;
    asm("fma.rn.f32x2 %0, %1, %2, %3;" : "=l"(d) : "l"(a), "l"(b), "l"(c));
    return d;
}
__device__ __forceinline__ void unpack2(unsigned long long v, float& lo, float& hi) {
    asm("mov.b64 {%0, %1}, %2;" : "=f"(lo), "=f"(hi) : "l"(v));
}

__device__ __forceinline__ int window_base(int grp_local) {
    int c = grp_local * GSIZE + GSIZE / 2;
    int b = c - WHALF;
    return min(max(b, 0), NPTS - NTILE * TILE);
}

// ---------------- kernel 1: partial histograms ----------------
__global__ void __launch_bounds__(HTHREADS)
hist_kernel(const float* __restrict__ pred, const float* __restrict__ targ) {
    __shared__ int h[NB];
    const int set   = blockIdx.x >> 5;
    const int slice = blockIdx.x & 31;
    const float* __restrict__ src = set ? targ : pred;
    const int tid = threadIdx.x;
    h[tid] = 0;
    __syncthreads();
#pragma unroll
    for (int r = 0; r < PPB / HTHREADS; r++) {
        const int i = slice * PPB + r * HTHREADS + tid;
        atomicAdd(&h[bucket_of(src[3 * i])], 1);
    }
    __syncthreads();
    g_part[blockIdx.x][tid] = h[tid];
}

// ---------------- kernel 2: prefix scan + per-call state reset ------------
__global__ void __launch_bounds__(2 * NB)
scan_kernel() {
    __shared__ int sVal[2 * NB];
    const int tid = threadIdx.x;
    const int set = tid >> 8;
    const int b   = tid & (NB - 1);
    if (tid == 0) { g_ucnt = 0; g_fsum = 0.0f; }

    int cnt = 0;
#pragma unroll 8
    for (int k = 0; k < 32; k++) cnt += g_part[set * 32 + k][b];
    sVal[tid] = cnt;
    __syncthreads();
    for (int st = 1; st < NB; st <<= 1) {
        int add = (b >= st) ? sVal[tid - st] : 0;
        __syncthreads();
        sVal[tid] += add;
        __syncthreads();
    }
    const int excl = sVal[tid] - cnt;
    g_boff[set][b] = excl;
    g_cur[set][b]  = excl;
    if (b == NB - 1) g_boff[set][NB] = sVal[tid];
}

// ---------------- kernel 3: scatter into bucket-sorted order --------------
__global__ void __launch_bounds__(HTHREADS)
scatter_kernel(const float* __restrict__ pred, const float* __restrict__ targ) {
    const int set   = blockIdx.x >> 5;
    const int slice = blockIdx.x & 31;
    const float* __restrict__ src = set ? targ : pred;
    const int tid = threadIdx.x;
#pragma unroll
    for (int r = 0; r < PPB / HTHREADS; r++) {
        const int i = slice * PPB + r * HTHREADS + tid;
        float x = src[3 * i + 0];
        float y = src[3 * i + 1];
        float z = src[3 * i + 2];
        int pos = atomicAdd(&g_cur[set][bucket_of(x)], 1);
        g_sorted[set][pos] = make_float4(x, y, z, x * x + y * y + z * z);
    }
}

// ---------------- kernel 4: phase A — flat windowed tile scan -------------
// 2048 CTAs of 64 threads: block = (group of 256 queries, tile of 128 ranks).
// KA=4 queries per thread keeps the 4xLDS.128 -> 24xFFMA2 mix; finer tiles
// double the resident-warp count (occ 15.6% -> ~40%).
__global__ void __launch_bounds__(MTHREADS)
phasea_kernel() {
    __shared__ __align__(16) float sx[TILE], sy[TILE], sz[TILE], sc[TILE];

    const int grp  = blockIdx.x >> 4;          // 0..127
    const int tile = blockIdx.x & 15;
    const int dir  = grp >> 6;
    const int grpl = grp & 63;
    const int aset = dir, bset = 1 - dir;
    const int tid  = threadIdx.x;

    const int t0 = window_base(grpl) + tile * TILE;
    const float4* __restrict__ B = g_sorted[bset];

    // stage tile (SoA): 64 threads x 2 float4, coalesced
#pragma unroll
    for (int r = 0; r < TILE / MTHREADS; r++) {
        const int s = tid + r * MTHREADS;
        float4 v = B[t0 + s];
        sx[s] = v.x; sy[s] = v.y; sz[s] = v.z; sc[s] = v.w;
    }

    // load KA query points
    const int q0 = grpl * GSIZE + tid;
    unsigned long long ax2[KA], ay2[KA], az2[KA];
    float mlo[KA], mhi[KA];
#pragma unroll
    for (int k = 0; k < KA; k++) {
        const float4 a = g_sorted[aset][q0 + k * MTHREADS];
        ax2[k] = pack2(-2.0f * a.x, -2.0f * a.x);
        ay2[k] = pack2(-2.0f * a.y, -2.0f * a.y);
        az2[k] = pack2(-2.0f * a.z, -2.0f * a.z);
        mlo[k] = POS_INF;
        mhi[k] = POS_INF;
    }
    __syncthreads();

#pragma unroll 4
    for (int j = 0; j < TILE; j += 4) {
        ulonglong2 vx = *(const ulonglong2*)&sx[j];
        ulonglong2 vy = *(const ulonglong2*)&sy[j];
        ulonglong2 vz = *(const ulonglong2*)&sz[j];
        ulonglong2 vc = *(const ulonglong2*)&sc[j];
#pragma unroll
        for (int k = 0; k < KA; k++) {
            unsigned long long s01 = fma2(ax2[k], vx.x, fma2(ay2[k], vy.x, fma2(az2[k], vz.x, vc.x)));
            unsigned long long s23 = fma2(ax2[k], vx.y, fma2(ay2[k], vy.y, fma2(az2[k], vz.y, vc.y)));
            float s0, s1, s2, s3;
            unpack2(s01, s0, s1);
            unpack2(s23, s2, s3);
            mlo[k] = fminf(mlo[k], fminf(s0, s2));
            mhi[k] = fminf(mhi[k], fminf(s1, s3));
        }
    }

#pragma unroll
    for (int k = 0; k < KA; k++)
        g_tmin[dir * NPTS + q0 + k * MTHREADS][tile] = fminf(mlo[k], mhi[k]);
}

// ---------------- kernel 5: resolve — reduce tiles, bound check -----------
// One thread per query; unresolved queries (conservative bucket-edge bound
// fails) are appended to a global list for the parallel fallback kernel.
__global__ void __launch_bounds__(RTHREADS)
resolve_kernel() {
    const int gq   = blockIdx.x * RTHREADS + threadIdx.x;  // 0..32767
    const int dir  = gq >> 14;
    const int q    = gq & (NPTS - 1);
    const int aset = dir, bset = 1 - dir;

    float m = POS_INF;
#pragma unroll
    for (int t = 0; t < NTILE; t++) m = fminf(m, g_tmin[gq][t]);

    const float4 a = g_sorted[aset][q];
    const float bound = fmaxf(a.w + m, 0.0f);      // best d^2 in window

    const int wlo = window_base(q >> 8);
    const int whi = wlo + NTILE * TILE;
    const float4* __restrict__ B = g_sorted[bset];

    bool unresolved = false;
    if (wlo > 0) {
        float eL  = right_edge(bucket_of(B[wlo].x));
        float dxl = fmaxf(a.x - eL, 0.0f);
        unresolved |= (dxl * dxl < bound);
    }
    if (whi < NPTS) {
        float eR  = left_edge(bucket_of(B[whi - 1].x));
        float dxr = fmaxf(eR - a.x, 0.0f);
        unresolved |= (dxr * dxr < bound);
    }

    float d = 0.0f;
    if (unresolved) {
        g_unres[atomicAdd(&g_ucnt, 1)] = gq;       // exact answer from fallback
    } else {
        d = sqrtf(bound);
    }

    __shared__ float sRed[RTHREADS / 32];
#pragma unroll
    for (int s = 16; s > 0; s >>= 1)
        d += __shfl_xor_sync(0xFFFFFFFFu, d, s);
    if ((threadIdx.x & 31) == 0) sRed[threadIdx.x >> 5] = d;
    __syncthreads();
    if (threadIdx.x == 0) {
        float t = 0.0f;
#pragma unroll
        for (int w = 0; w < RTHREADS / 32; w++) t += sRed[w];
        g_partial[blockIdx.x] = t;
    }
}

// ---------------- kernel 6: fallback — warp-per-query exact scan ----------
// 512 warps stride the unresolved list; each warp scans all 16K candidates
// (512 per lane) and atomically adds the exact distance. Clustered unresolved
// queries parallelize perfectly (the R11 fusion serialized them).
__global__ void __launch_bounds__(FBTHREADS)
fallback_kernel() {
    const int nwarps = FBBLOCKS * FBTHREADS / 32;
    const int wid    = (blockIdx.x * FBTHREADS + threadIdx.x) >> 5;
    const int lane   = threadIdx.x & 31;
    const int cnt    = g_ucnt;

    for (int i = wid; i < cnt; i += nwarps) {
        const int gq   = g_unres[i];
        const int dir  = gq >> 14;
        const int q    = gq & (NPTS - 1);
        const float4 a = g_sorted[dir][q];
        const float amx = -2.0f * a.x, amy = -2.0f * a.y, amz = -2.0f * a.z;
        const float4* __restrict__ B = g_sorted[1 - dir];

        float m = POS_INF;
#pragma unroll 4
        for (int j = lane; j < NPTS; j += 32) {
            float4 b = B[j];
            float s = fmaf(amx, b.x, fmaf(amy, b.y, fmaf(amz, b.z, b.w)));
            m = fminf(m, s);
        }
#pragma unroll
        for (int s = 16; s > 0; s >>= 1)
            m = fminf(m, __shfl_xor_sync(0xFFFFFFFFu, m, s));
        if (lane == 0)
            atomicAdd(&g_fsum, sqrtf(fmaxf(a.w + m, 0.0f)));
    }
}

// ---------------- kernel 7: final sum ----------------
__global__ void __launch_bounds__(RBLOCKS)
final_kernel(float* __restrict__ out) {
    float v = g_partial[threadIdx.x];
#pragma unroll
    for (int s = 16; s > 0; s >>= 1)
        v += __shfl_xor_sync(0xFFFFFFFFu, v, s);
    __shared__ float sRed[RBLOCKS / 32];
    if ((threadIdx.x & 31) == 0) sRed[threadIdx.x >> 5] = v;
    __syncthreads();
    if (threadIdx.x == 0) {
        float t = g_fsum;
#pragma unroll
        for (int w = 0; w < RBLOCKS / 32; w++) t += sRed[w];
        out[0] = t * (1.0f / (float)NPTS);
    }
}

// ---------------- launch ----------------
extern "C" void kernel_launch(void* const* d_in, const int* in_sizes, int n_in,
                              void* d_out, int out_size) {
    const float* pred = (const float*)d_in[0];
    const float* targ = (const float*)d_in[1];
    float* out = (float*)d_out;

    hist_kernel<<<HBLOCKS, HTHREADS>>>(pred, targ);
    scan_kernel<<<1, 2 * NB>>>();
    scatter_kernel<<<HBLOCKS, HTHREADS>>>(pred, targ);
    phasea_kernel<<<NGRP * NTILE, MTHREADS>>>();
    resolve_kernel<<<2 * NPTS / RTHREADS, RTHREADS>>>();
    fallback_kernel<<<FBBLOCKS, FBTHREADS>>>();
    final_kernel<<<1, RBLOCKS>>>(out);
}

// round 13
// speedup vs baseline: 5.1588x; 3.2544x over previous
#include <cuda_runtime.h>
#include <cstdint>

#define NPTS     16384
#define NB       256
#define XMIN     (-4.0f)
#define BW       0.03125f           // 8/256, exact in binary
#define INVBW    32.0f
#define HBLOCKS  64                 // hist/scatter blocks (32 per set)
#define HTHREADS 256
#define PPB      512                // points per hist/scatter block
#define GSIZE    256                // queries per group
#define NGRP     128                // 64 per direction
#define MTHREADS 64                 // phase-A block size
#define KA       4                  // queries per thread
#define NTILE    16                 // window tiles per group
#define TILE     128                // ranks per tile  (window = 2048 ranks)
#define WHALF    1024
#define RBLOCKS  128
#define RTHREADS 256
#define FBBLOCKS 256
#define FBTHREADS 256

#define POS_INF __int_as_float(0x7f800000)

// ---------------- persistent scratch (rewritten every call) ----------------
__device__ int    g_part[HBLOCKS][NB];       // per-block partial histograms
__device__ int    g_boff[2][NB + 1];         // bucket start offsets
__device__ int    g_cur[2][NB];              // scatter cursors
__device__ float4 g_sorted[2][NPTS];         // (x,y,z,|p|^2), bucket-sorted by x
__device__ float  g_tmin[2 * NPTS][NTILE];   // per-(query,tile) partial mins (2 MB)
__device__ float  g_partial[RBLOCKS];        // resolve-block sums
__device__ int    g_unres[2 * NPTS];         // unresolved query list
__device__ float  g_ubound[2 * NPTS];        // window-best d^2 for unresolved
__device__ int    g_ucnt;                    // list count
__device__ float  g_fsum;                    // fallback sum

__device__ __forceinline__ int bucket_of(float x) {
    int b = (int)floorf((x - XMIN) * INVBW);
    return min(max(b, 0), NB - 1);
}
// unseen-left points (rank < lo) lie in buckets <= bucket_of(B[lo].x): x < right edge
__device__ __forceinline__ float right_edge(int b) {
    return (b >= NB - 1) ? 1e30f : (XMIN + (float)(b + 1) * BW);
}
// unseen-right points (rank >= hi) lie in buckets >= bucket_of(B[hi-1].x): x >= left edge
__device__ __forceinline__ float left_edge(int b) {
    return (b <= 0) ? -1e30f : (XMIN + (float)b * BW);
}

// ---------------- packed f32x2 helpers ----------------
__device__ __forceinline__ unsigned long long pack2(float lo, float hi) {
    unsigned long long r;
    asm("mov.b64 %0, {%1, %2};" : "=l"(r) : "f"(lo), "f"(hi));
    return r;
}
__device__ __forceinline__ unsigned long long fma2(unsigned long long a,
                                                   unsigned long long b,
                                                   unsigned long long c) {
    unsigned long long d;
    asm("fma.rn.f32x2 %0, %1, %2, %3;" : "=l"(d) : "l"(a), "l"(b), "l"(c));
    return d;
}
__device__ __forceinline__ void unpack2(unsigned long long v, float& lo, float& hi) {
    asm("mov.b64 {%0, %1}, %2;" : "=f"(lo), "=f"(hi) : "l"(v));
}

__device__ __forceinline__ int window_base(int grp_local) {
    int c = grp_local * GSIZE + GSIZE / 2;
    int b = c - WHALF;
    return min(max(b, 0), NPTS - NTILE * TILE);
}

// ---------------- kernel 1: partial histograms ----------------
__global__ void __launch_bounds__(HTHREADS)
hist_kernel(const float* __restrict__ pred, const float* __restrict__ targ) {
    __shared__ int h[NB];
    const int set   = blockIdx.x >> 5;
    const int slice = blockIdx.x & 31;
    const float* __restrict__ src = set ? targ : pred;
    const int tid = threadIdx.x;
    h[tid] = 0;
    __syncthreads();
#pragma unroll
    for (int r = 0; r < PPB / HTHREADS; r++) {
        const int i = slice * PPB + r * HTHREADS + tid;
        atomicAdd(&h[bucket_of(src[3 * i])], 1);
    }
    __syncthreads();
    g_part[blockIdx.x][tid] = h[tid];
}

// ---------------- kernel 2: prefix scan + per-call state reset ------------
__global__ void __launch_bounds__(2 * NB)
scan_kernel() {
    __shared__ int sVal[2 * NB];
    const int tid = threadIdx.x;
    const int set = tid >> 8;
    const int b   = tid & (NB - 1);
    if (tid == 0) { g_ucnt = 0; g_fsum = 0.0f; }

    int cnt = 0;
#pragma unroll 8
    for (int k = 0; k < 32; k++) cnt += g_part[set * 32 + k][b];
    sVal[tid] = cnt;
    __syncthreads();
    for (int st = 1; st < NB; st <<= 1) {
        int add = (b >= st) ? sVal[tid - st] : 0;
        __syncthreads();
        sVal[tid] += add;
        __syncthreads();
    }
    const int excl = sVal[tid] - cnt;
    g_boff[set][b] = excl;
    g_cur[set][b]  = excl;
    if (b == NB - 1) g_boff[set][NB] = sVal[tid];
}

// ---------------- kernel 3: scatter into bucket-sorted order --------------
__global__ void __launch_bounds__(HTHREADS)
scatter_kernel(const float* __restrict__ pred, const float* __restrict__ targ) {
    const int set   = blockIdx.x >> 5;
    const int slice = blockIdx.x & 31;
    const float* __restrict__ src = set ? targ : pred;
    const int tid = threadIdx.x;
#pragma unroll
    for (int r = 0; r < PPB / HTHREADS; r++) {
        const int i = slice * PPB + r * HTHREADS + tid;
        float x = src[3 * i + 0];
        float y = src[3 * i + 1];
        float z = src[3 * i + 2];
        int pos = atomicAdd(&g_cur[set][bucket_of(x)], 1);
        g_sorted[set][pos] = make_float4(x, y, z, x * x + y * y + z * z);
    }
}

// ---------------- kernel 4: phase A — flat windowed tile scan -------------
// 2048 CTAs of 64 threads: block = (group of 256 queries, tile of 128 ranks).
// KA=4 queries per thread: every 4xLDS.128 batch feeds 24 packed FFMA2.
__global__ void __launch_bounds__(MTHREADS)
phasea_kernel() {
    __shared__ __align__(16) float sx[TILE], sy[TILE], sz[TILE], sc[TILE];

    const int grp  = blockIdx.x >> 4;          // 0..127
    const int tile = blockIdx.x & 15;
    const int dir  = grp >> 6;
    const int grpl = grp & 63;
    const int aset = dir, bset = 1 - dir;
    const int tid  = threadIdx.x;

    const int t0 = window_base(grpl) + tile * TILE;
    const float4* __restrict__ B = g_sorted[bset];

#pragma unroll
    for (int r = 0; r < TILE / MTHREADS; r++) {
        const int s = tid + r * MTHREADS;
        float4 v = B[t0 + s];
        sx[s] = v.x; sy[s] = v.y; sz[s] = v.z; sc[s] = v.w;
    }

    const int q0 = grpl * GSIZE + tid;
    unsigned long long ax2[KA], ay2[KA], az2[KA];
    float mlo[KA], mhi[KA];
#pragma unroll
    for (int k = 0; k < KA; k++) {
        const float4 a = g_sorted[aset][q0 + k * MTHREADS];
        ax2[k] = pack2(-2.0f * a.x, -2.0f * a.x);
        ay2[k] = pack2(-2.0f * a.y, -2.0f * a.y);
        az2[k] = pack2(-2.0f * a.z, -2.0f * a.z);
        mlo[k] = POS_INF;
        mhi[k] = POS_INF;
    }
    __syncthreads();

#pragma unroll 4
    for (int j = 0; j < TILE; j += 4) {
        ulonglong2 vx = *(const ulonglong2*)&sx[j];
        ulonglong2 vy = *(const ulonglong2*)&sy[j];
        ulonglong2 vz = *(const ulonglong2*)&sz[j];
        ulonglong2 vc = *(const ulonglong2*)&sc[j];
#pragma unroll
        for (int k = 0; k < KA; k++) {
            unsigned long long s01 = fma2(ax2[k], vx.x, fma2(ay2[k], vy.x, fma2(az2[k], vz.x, vc.x)));
            unsigned long long s23 = fma2(ax2[k], vx.y, fma2(ay2[k], vy.y, fma2(az2[k], vz.y, vc.y)));
            float s0, s1, s2, s3;
            unpack2(s01, s0, s1);
            unpack2(s23, s2, s3);
            mlo[k] = fminf(mlo[k], fminf(s0, s2));
            mhi[k] = fminf(mhi[k], fminf(s1, s3));
        }
    }

#pragma unroll
    for (int k = 0; k < KA; k++)
        g_tmin[dir * NPTS + q0 + k * MTHREADS][tile] = fminf(mlo[k], mhi[k]);
}

// ---------------- kernel 5: resolve — reduce tiles, bound check -----------
__global__ void __launch_bounds__(RTHREADS)
resolve_kernel() {
    const int gq   = blockIdx.x * RTHREADS + threadIdx.x;  // 0..32767
    const int dir  = gq >> 14;
    const int q    = gq & (NPTS - 1);
    const int aset = dir, bset = 1 - dir;

    float m = POS_INF;
#pragma unroll
    for (int t = 0; t < NTILE; t++) m = fminf(m, g_tmin[gq][t]);

    const float4 a = g_sorted[aset][q];
    const float bound = fmaxf(a.w + m, 0.0f);      // best d^2 in window

    const int wlo = window_base(q >> 8);
    const int whi = wlo + NTILE * TILE;
    const float4* __restrict__ B = g_sorted[bset];

    bool unresolved = false;
    if (wlo > 0) {
        float eL  = right_edge(bucket_of(B[wlo].x));
        float dxl = fmaxf(a.x - eL, 0.0f);
        unresolved |= (dxl * dxl < bound);
    }
    if (whi < NPTS) {
        float eR  = left_edge(bucket_of(B[whi - 1].x));
        float dxr = fmaxf(eR - a.x, 0.0f);
        unresolved |= (dxr * dxr < bound);
    }

    float d = 0.0f;
    if (unresolved) {
        int slot = atomicAdd(&g_ucnt, 1);
        g_unres[slot]  = gq;                       // exact answer from fallback
        g_ubound[slot] = bound;
    } else {
        d = sqrtf(bound);
    }

    __shared__ float sRed[RTHREADS / 32];
#pragma unroll
    for (int s = 16; s > 0; s >>= 1)
        d += __shfl_xor_sync(0xFFFFFFFFu, d, s);
    if ((threadIdx.x & 31) == 0) sRed[threadIdx.x >> 5] = d;
    __syncthreads();
    if (threadIdx.x == 0) {
        float t = 0.0f;
#pragma unroll
        for (int w = 0; w < RTHREADS / 32; w++) t += sRed[w];
        g_partial[blockIdx.x] = t;
    }
}

// ---------------- kernel 6: fallback — block-per-query, x-range pruned ----
// Any point beating `bound` has |dx| < sqrt(bound); bucket_of is monotone in
// x, so candidates form the contiguous rank range
// [boff[bucket(x-d)], boff[bucket(x+d)+1]). Typically a few thousand ranks.
// 256-thread blocks, coalesced float4 loads -> high MLP per query.
__global__ void __launch_bounds__(FBTHREADS)
fallback_kernel() {
    __shared__ float sMin[FBTHREADS / 32];
    const int tid = threadIdx.x;
    const int cnt = g_ucnt;

    for (int i = blockIdx.x; i < cnt; i += FBBLOCKS) {
        const int   gq    = g_unres[i];
        const float bound = g_ubound[i];
        const int   dir   = gq >> 14;
        const int   q     = gq & (NPTS - 1);
        const float4 a = g_sorted[dir][q];
        const float amx = -2.0f * a.x, amy = -2.0f * a.y, amz = -2.0f * a.z;
        const float4* __restrict__ B = g_sorted[1 - dir];
        const int* __restrict__ boff = g_boff[1 - dir];

        const float dmax = sqrtf(bound);
        const int rlo = boff[bucket_of(a.x - dmax)];
        const int rhi = boff[bucket_of(a.x + dmax) + 1];

        float m = POS_INF;
        for (int j = rlo + tid; j < rhi; j += FBTHREADS) {
            float4 b = B[j];
            float s = fmaf(amx, b.x, fmaf(amy, b.y, fmaf(amz, b.z, b.w)));
            m = fminf(m, s);
        }
#pragma unroll
        for (int s = 16; s > 0; s >>= 1)
            m = fminf(m, __shfl_xor_sync(0xFFFFFFFFu, m, s));
        if ((tid & 31) == 0) sMin[tid >> 5] = m;
        __syncthreads();
        if (tid == 0) {
            float mm = POS_INF;
#pragma unroll
            for (int w = 0; w < FBTHREADS / 32; w++) mm = fminf(mm, sMin[w]);
            mm = fminf(mm, bound - a.w);           // window best already known
            atomicAdd(&g_fsum, sqrtf(fmaxf(a.w + mm, 0.0f)));
        }
        __syncthreads();
    }
}

// ---------------- kernel 7: final sum ----------------
__global__ void __launch_bounds__(RBLOCKS)
final_kernel(float* __restrict__ out) {
    float v = g_partial[threadIdx.x];
#pragma unroll
    for (int s = 16; s > 0; s >>= 1)
        v += __shfl_xor_sync(0xFFFFFFFFu, v, s);
    __shared__ float sRed[RBLOCKS / 32];
    if ((threadIdx.x & 31) == 0) sRed[threadIdx.x >> 5] = v;
    __syncthreads();
    if (threadIdx.x == 0) {
        float t = g_fsum;
#pragma unroll
        for (int w = 0; w < RBLOCKS / 32; w++) t += sRed[w];
        out[0] = t * (1.0f / (float)NPTS);
    }
}

// ---------------- launch ----------------
extern "C" void kernel_launch(void* const* d_in, const int* in_sizes, int n_in,
                              void* d_out, int out_size) {
    const float* pred = (const float*)d_in[0];
    const float* targ = (const float*)d_in[1];
    float* out = (float*)d_out;

    hist_kernel<<<HBLOCKS, HTHREADS>>>(pred, targ);
    scan_kernel<<<1, 2 * NB>>>();
    scatter_kernel<<<HBLOCKS, HTHREADS>>>(pred, targ);
    phasea_kernel<<<NGRP * NTILE, MTHREADS>>>();
    resolve_kernel<<<2 * NPTS / RTHREADS, RTHREADS>>>();
    fallback_kernel<<<FBBLOCKS, FBTHREADS>>>();
    final_kernel<<<1, RBLOCKS>>>(out);
}

// round 16
// speedup vs baseline: 5.2684x; 1.0213x over previous
#include <cuda_runtime.h>
#include <cstdint>

#define NPTS     16384
#define NB       256
#define XMIN     (-4.0f)
#define BW       0.03125f           // 8/256, exact in binary
#define INVBW    32.0f
#define HBLOCKS  64                 // hist/scatter blocks (32 per set)
#define HTHREADS 256
#define PPB      512                // points per hist/scatter block
#define GSIZE    512                // queries per group
#define NGRP     64                 // 32 per direction
#define MTHREADS 128                // phase-A block size (4 warps)
#define KA       4                  // queries per thread
#define NTILE    8                  // window tiles per group
#define TILE     256                // ranks per tile  (window = 2048 ranks)
#define WHALF    1024
#define RBLOCKS  128
#define RTHREADS 256
#define FBBLOCKS 256
#define FBTHREADS 256

#define POS_INF __int_as_float(0x7f800000)

// ---------------- persistent scratch (reset by hist each call) -------------
__device__ int    g_part[HBLOCKS][NB];       // per-block partial histograms
__device__ int    g_boff[2][NB + 1];         // bucket start offsets
__device__ int    g_cur[2][NB];              // scatter delta cursors
__device__ float4 g_sorted[2][NPTS];         // (x,y,z,|p|^2), bucket-sorted by x
__device__ float  g_tmin[2 * NPTS][NTILE];   // per-(query,tile) partial mins (1 MB)
__device__ float  g_partial[RBLOCKS];        // resolve-block sums
__device__ int    g_unres[2 * NPTS];         // unresolved query list
__device__ float  g_ubound[2 * NPTS];        // window-best d^2 for unresolved
__device__ int    g_ucnt;                    // list count
__device__ float  g_fsum;                    // fallback sum

__device__ __forceinline__ int bucket_of(float x) {
    int b = (int)floorf((x - XMIN) * INVBW);
    return min(max(b, 0), NB - 1);
}
// unseen-left points (rank < lo) lie in buckets <= bucket_of(B[lo].x): x < right edge
__device__ __forceinline__ float right_edge(int b) {
    return (b >= NB - 1) ? 1e30f : (XMIN + (float)(b + 1) * BW);
}
// unseen-right points (rank >= hi) lie in buckets >= bucket_of(B[hi-1].x): x >= left edge
__device__ __forceinline__ float left_edge(int b) {
    return (b <= 0) ? -1e30f : (XMIN + (float)b * BW);
}

// ---------------- packed f32x2 helpers ----------------
__device__ __forceinline__ unsigned long long pack2(float lo, float hi) {
    unsigned long long r;
    asm("mov.b64 %0, {%1, %2};" : "=l"(r) : "f"(lo), "f"(hi));
    return r;
}
__device__ __forceinline__ unsigned long long fma2(unsigned long long a,
                                                   unsigned long long b,
                                                   unsigned long long c) {
    unsigned long long d;
    asm("fma.rn.f32x2 %0, %1, %2, %3;" : "=l"(d) : "l"(a), "l"(b), "l"(c));
    return d;
}
__device__ __forceinline__ void unpack2(unsigned long long v, float& lo, float& hi) {
    asm("mov.b64 {%0, %1}, %2;" : "=f"(lo), "=f"(hi) : "l"(v));
}

__device__ __forceinline__ int window_base(int grp_local) {
    int c = grp_local * GSIZE + GSIZE / 2;
    int b = c - WHALF;
    return min(max(b, 0), NPTS - NTILE * TILE);
}

// ---------------- kernel 1: partial histograms + per-call state reset -----
__global__ void __launch_bounds__(HTHREADS)
hist_kernel(const float* __restrict__ pred, const float* __restrict__ targ) {
    __shared__ int h[NB];
    const int set   = blockIdx.x >> 5;
    const int slice = blockIdx.x & 31;
    const float* __restrict__ src = set ? targ : pred;
    const int tid = threadIdx.x;

    // distributed reset of mutable state (plain writes; replay-safe)
    if (tid < 8) {
        ((int*)g_cur)[blockIdx.x * 8 + tid] = 0;   // 64 blocks x 8 = 512 ints
    }
    if (blockIdx.x == 0 && tid == 0) { g_ucnt = 0; g_fsum = 0.0f; }

    h[tid] = 0;
    __syncthreads();
#pragma unroll
    for (int r = 0; r < PPB / HTHREADS; r++) {
        const int i = slice * PPB + r * HTHREADS + tid;
        atomicAdd(&h[bucket_of(src[3 * i])], 1);
    }
    __syncthreads();
    g_part[blockIdx.x][tid] = h[tid];
}

// ---------------- kernel 2: fused scan + scatter --------------------------
// Each block recomputes its set's 256-bucket prefix scan locally from g_part
// (L2-hot), then scatters its 512 points with excl[b] + global delta cursor.
// slice-0 blocks also publish g_boff for resolve/fallback.
__global__ void __launch_bounds__(HTHREADS)
scatter_kernel(const float* __restrict__ pred, const float* __restrict__ targ) {
    __shared__ int sVal[NB];
    __shared__ int sExcl[NB];
    const int set   = blockIdx.x >> 5;
    const int slice = blockIdx.x & 31;
    const float* __restrict__ src = set ? targ : pred;
    const int tid = threadIdx.x;

    int cnt = 0;
#pragma unroll 8
    for (int k = 0; k < 32; k++) cnt += g_part[set * 32 + k][tid];
    sVal[tid] = cnt;
    __syncthreads();
    for (int st = 1; st < NB; st <<= 1) {
        int add = (tid >= st) ? sVal[tid - st] : 0;
        __syncthreads();
        sVal[tid] += add;
        __syncthreads();
    }
    sExcl[tid] = sVal[tid] - cnt;
    if (slice == 0) {
        g_boff[set][tid] = sVal[tid] - cnt;
        if (tid == NB - 1) g_boff[set][NB] = sVal[tid];
    }
    __syncthreads();

#pragma unroll
    for (int r = 0; r < PPB / HTHREADS; r++) {
        const int i = slice * PPB + r * HTHREADS + tid;
        float x = src[3 * i + 0];
        float y = src[3 * i + 1];
        float z = src[3 * i + 2];
        const int b = bucket_of(x);
        int pos = sExcl[b] + atomicAdd(&g_cur[set][b], 1);
        g_sorted[set][pos] = make_float4(x, y, z, x * x + y * y + z * z);
    }
}

// ---------------- kernel 3: phase A — flat windowed tile scan -------------
// 512 CTAs of 128 threads: block = (group of 512 queries, tile of 256 ranks).
// KA=4 queries/thread keeps the 4xLDS.128 -> 24xFFMA2 mix; 256-rank tiles
// halve per-block fixed overhead vs TILE=128.
__global__ void __launch_bounds__(MTHREADS)
phasea_kernel() {
    __shared__ __align__(16) float sx[TILE], sy[TILE], sz[TILE], sc[TILE];

    const int grp  = blockIdx.x >> 3;          // 0..63
    const int tile = blockIdx.x & 7;
    const int dir  = grp >> 5;
    const int grpl = grp & 31;
    const int aset = dir, bset = 1 - dir;
    const int tid  = threadIdx.x;

    const int t0 = window_base(grpl) + tile * TILE;
    const float4* __restrict__ B = g_sorted[bset];

#pragma unroll
    for (int r = 0; r < TILE / MTHREADS; r++) {
        const int s = tid + r * MTHREADS;
        float4 v = B[t0 + s];
        sx[s] = v.x; sy[s] = v.y; sz[s] = v.z; sc[s] = v.w;
    }

    const int q0 = grpl * GSIZE + tid;
    unsigned long long ax2[KA], ay2[KA], az2[KA];
    float mlo[KA], mhi[KA];
#pragma unroll
    for (int k = 0; k < KA; k++) {
        const float4 a = g_sorted[aset][q0 + k * MTHREADS];
        ax2[k] = pack2(-2.0f * a.x, -2.0f * a.x);
        ay2[k] = pack2(-2.0f * a.y, -2.0f * a.y);
        az2[k] = pack2(-2.0f * a.z, -2.0f * a.z);
        mlo[k] = POS_INF;
        mhi[k] = POS_INF;
    }
    __syncthreads();

#pragma unroll 4
    for (int j = 0; j < TILE; j += 4) {
        ulonglong2 vx = *(const ulonglong2*)&sx[j];
        ulonglong2 vy = *(const ulonglong2*)&sy[j];
        ulonglong2 vz = *(const ulonglong2*)&sz[j];
        ulonglong2 vc = *(const ulonglong2*)&sc[j];
#pragma unroll
        for (int k = 0; k < KA; k++) {
            unsigned long long s01 = fma2(ax2[k], vx.x, fma2(ay2[k], vy.x, fma2(az2[k], vz.x, vc.x)));
            unsigned long long s23 = fma2(ax2[k], vx.y, fma2(ay2[k], vy.y, fma2(az2[k], vz.y, vc.y)));
            float s0, s1, s2, s3;
            unpack2(s01, s0, s1);
            unpack2(s23, s2, s3);
            mlo[k] = fminf(mlo[k], fminf(s0, s2));
            mhi[k] = fminf(mhi[k], fminf(s1, s3));
        }
    }

#pragma unroll
    for (int k = 0; k < KA; k++)
        g_tmin[dir * NPTS + q0 + k * MTHREADS][tile] = fminf(mlo[k], mhi[k]);
}

// ---------------- kernel 4: resolve — reduce tiles, bound check -----------
__global__ void __launch_bounds__(RTHREADS)
resolve_kernel() {
    const int gq   = blockIdx.x * RTHREADS + threadIdx.x;  // 0..32767
    const int dir  = gq >> 14;
    const int q    = gq & (NPTS - 1);
    const int aset = dir, bset = 1 - dir;

    float m = POS_INF;
#pragma unroll
    for (int t = 0; t < NTILE; t++) m = fminf(m, g_tmin[gq][t]);

    const float4 a = g_sorted[aset][q];
    const float bound = fmaxf(a.w + m, 0.0f);      // best d^2 in window

    const int wlo = window_base(q >> 9);
    const int whi = wlo + NTILE * TILE;
    const float4* __restrict__ B = g_sorted[bset];

    bool unresolved = false;
    if (wlo > 0) {
        float eL  = right_edge(bucket_of(B[wlo].x));
        float dxl = fmaxf(a.x - eL, 0.0f);
        unresolved |= (dxl * dxl < bound);
    }
    if (whi < NPTS) {
        float eR  = left_edge(bucket_of(B[whi - 1].x));
        float dxr = fmaxf(eR - a.x, 0.0f);
        unresolved |= (dxr * dxr < bound);
    }

    float d = 0.0f;
    if (unresolved) {
        int slot = atomicAdd(&g_ucnt, 1);
        g_unres[slot]  = gq;                       // exact answer from fallback
        g_ubound[slot] = bound;
    } else {
        d = sqrtf(bound);
    }

    __shared__ float sRed[RTHREADS / 32];
#pragma unroll
    for (int s = 16; s > 0; s >>= 1)
        d += __shfl_xor_sync(0xFFFFFFFFu, d, s);
    if ((threadIdx.x & 31) == 0) sRed[threadIdx.x >> 5] = d;
    __syncthreads();
    if (threadIdx.x == 0) {
        float t = 0.0f;
#pragma unroll
        for (int w = 0; w < RTHREADS / 32; w++) t += sRed[w];
        g_partial[blockIdx.x] = t;
    }
}

// ---------------- kernel 5: fallback — block-per-query, x-range pruned ----
// Any point beating `bound` has |dx| < sqrt(bound); candidates form the
// contiguous rank range [boff[bucket(x-d)], boff[bucket(x+d)+1]).
__global__ void __launch_bounds__(FBTHREADS)
fallback_kernel() {
    __shared__ float sMin[FBTHREADS / 32];
    const int tid = threadIdx.x;
    const int cnt = g_ucnt;

    for (int i = blockIdx.x; i < cnt; i += FBBLOCKS) {
        const int   gq    = g_unres[i];
        const float bound = g_ubound[i];
        const int   dir   = gq >> 14;
        const int   q     = gq & (NPTS - 1);
        const float4 a = g_sorted[dir][q];
        const float amx = -2.0f * a.x, amy = -2.0f * a.y, amz = -2.0f * a.z;
        const float4* __restrict__ B = g_sorted[1 - dir];
        const int* __restrict__ boff = g_boff[1 - dir];

        const float dmax = sqrtf(bound);
        const int rlo = boff[bucket_of(a.x - dmax)];
        const int rhi = boff[bucket_of(a.x + dmax) + 1];

        float m = POS_INF;
        for (int j = rlo + tid; j < rhi; j += FBTHREADS) {
            float4 b = B[j];
            float s = fmaf(amx, b.x, fmaf(amy, b.y, fmaf(amz, b.z, b.w)));
            m = fminf(m, s);
        }
#pragma unroll
        for (int s = 16; s > 0; s >>= 1)
            m = fminf(m, __shfl_xor_sync(0xFFFFFFFFu, m, s));
        if ((tid & 31) == 0) sMin[tid >> 5] = m;
        __syncthreads();
        if (tid == 0) {
            float mm = POS_INF;
#pragma unroll
            for (int w = 0; w < FBTHREADS / 32; w++) mm = fminf(mm, sMin[w]);
            mm = fminf(mm, bound - a.w);           // window best already known
            atomicAdd(&g_fsum, sqrtf(fmaxf(a.w + mm, 0.0f)));
        }
        __syncthreads();
    }
}

// ---------------- kernel 6: final sum ----------------
__global__ void __launch_bounds__(RBLOCKS)
final_kernel(float* __restrict__ out) {
    float v = g_partial[threadIdx.x];
#pragma unroll
    for (int s = 16; s > 0; s >>= 1)
        v += __shfl_xor_sync(0xFFFFFFFFu, v, s);
    __shared__ float sRed[RBLOCKS / 32];
    if ((threadIdx.x & 31) == 0) sRed[threadIdx.x >> 5] = v;
    __syncthreads();
    if (threadIdx.x == 0) {
        float t = g_fsum;
#pragma unroll
        for (int w = 0; w < RBLOCKS / 32; w++) t += sRed[w];
        out[0] = t * (1.0f / (float)NPTS);
    }
}

// ---------------- launch ----------------
extern "C" void kernel_launch(void* const* d_in, const int* in_sizes, int n_in,
                              void* d_out, int out_size) {
    const float* pred = (const float*)d_in[0];
    const float* targ = (const float*)d_in[1];
    float* out = (float*)d_out;

    hist_kernel<<<HBLOCKS, HTHREADS>>>(pred, targ);
    scatter_kernel<<<HBLOCKS, HTHREADS>>>(pred, targ);
    phasea_kernel<<<NGRP * NTILE, MTHREADS>>>();
    resolve_kernel<<<2 * NPTS / RTHREADS, RTHREADS>>>();
    fallback_kernel<<<FBBLOCKS, FBTHREADS>>>();
    final_kernel<<<1, RBLOCKS>>>(out);
}